// round 14
// baseline (speedup 1.0000x reference)
#include <cuda_runtime.h>
#include <cuda_fp16.h>
#include <cuda_bf16.h>
#include <cstdint>

#define DIM    192
#define HEADS  4
#define D      48
#define HW     4096
#define BKT    64              // keys per tile
#define SPLITS 8
#define SKEYS  (HW / SPLITS)   // 512 keys per split
#define NTT    (SKEYS / BKT)   // 8 tiles per split
#define KS12   12              // 192/16 k-steps for the 1x1 convs

// fragment array sizes (entries)
#define QF_LANES (HEADS * 256 * 3 * 32)          // uint4 entries
#define KF_LANES (HEADS * 64 * 3 * 8 * 32)       // uint2 entries
#define VF_LANES (HEADS * 64 * 4 * 6 * 32)       // uint2 entries
#define WQF_ENT  (36 * KS12 * 32)                // uint4: w_qkv A-frags
#define WPF_ENT  (12 * KS12 * 32)                // uint4: w_proj A-frags
#define XF_ENT   (KS12 * 512 * 32)               // uint2: x B-frags
#define AF_ENT   (KS12 * 512 * 32)               // uint2: att B-frags

// ---------------- scratch ----------------
__device__ __half   g_qkv1[3 * DIM * HW];
__device__ __half   g_qkv2[3 * DIM * HW];
__device__ float    g_invq[HEADS * HW];
__device__ float    g_invk[HEADS * HW];
__device__ uint32_t g_po  [SPLITS * HEADS * 24 * HW];   // packed half2 pairs
__device__ float    g_pl  [SPLITS * HEADS * HW];
__device__ uint4    g_Qf [QF_LANES];
__device__ uint2    g_Kf [KF_LANES];
__device__ uint2    g_Vf [VF_LANES];
__device__ uint4    g_Wqf[WQF_ENT];
__device__ uint4    g_Wpf[WPF_ENT];
__device__ uint2    g_Xf [XF_ENT];
__device__ uint2    g_Af [AF_ENT];

// ---------------- helpers ----------------
__device__ __forceinline__ uint32_t packh(float hi, float lo) {
    uint32_t r; asm("cvt.rn.f16x2.f32 %0, %1, %2;" : "=r"(r) : "f"(hi), "f"(lo));
    return r;
}
__device__ __forceinline__ uint32_t ex2h2(uint32_t x) {
    uint32_t y; asm("ex2.approx.f16x2 %0, %1;" : "=r"(y) : "r"(x));
    return y;
}
__device__ __forceinline__ void mma16(float* d, const uint32_t* a, uint2 b) {
    asm volatile("mma.sync.aligned.m16n8k16.row.col.f32.f16.f16.f32 "
        "{%0,%1,%2,%3}, {%4,%5,%6,%7}, {%8,%9}, {%0,%1,%2,%3};"
        : "+f"(d[0]), "+f"(d[1]), "+f"(d[2]), "+f"(d[3])
        : "r"(a[0]), "r"(a[1]), "r"(a[2]), "r"(a[3]),
          "r"(b.x), "r"(b.y));
}
__device__ __forceinline__ uint32_t smem_u32(const void* p) {
    uint32_t a;
    asm("{ .reg .u64 t; cvta.to.shared.u64 t, %1; cvt.u32.u64 %0, t; }"
        : "=r"(a) : "l"(p));
    return a;
}
__device__ __forceinline__ void cpasync16(uint32_t saddr, const void* gptr) {
    asm volatile("cp.async.ca.shared.global [%0], [%1], 16;"
                 :: "r"(saddr), "l"(gptr) : "memory");
}
#define CP_COMMIT()  asm volatile("cp.async.commit_group;" ::: "memory")
#define CP_WAIT(n)   asm volatile("cp.async.wait_group %0;" :: "n"(n) : "memory")

// ---------------- merged weight + x fragment prep (fp16) -------------------
__global__ __launch_bounds__(256) void prep0_kernel(
    const float* __restrict__ w_qkv, const float* __restrict__ w_proj,
    const float* __restrict__ x,
    uint4* __restrict__ Wqf, uint4* __restrict__ Wpf, uint2* __restrict__ Xf)
{
    int idx = blockIdx.x * 256 + threadIdx.x;
    if (idx < WQF_ENT + WPF_ENT) {
        const float* W;
        uint4* dst;
        int i;
        if (idx < WQF_ENT) { W = w_qkv; dst = Wqf; i = idx; }
        else { W = w_proj; dst = Wpf; i = idx - WQF_ENT; }
        int lane = i & 31; int r = i >> 5;
        int ks = r % KS12; int mrb = r / KS12;
        int g = lane >> 2, tig = lane & 3;
        int row0 = mrb * 16 + g;
        int db = ks * 16 + 2 * tig;
        uint4 v;
        v.x = packh(W[row0 * DIM + db + 1],       W[row0 * DIM + db]);
        v.y = packh(W[(row0 + 8) * DIM + db + 1], W[(row0 + 8) * DIM + db]);
        v.z = packh(W[row0 * DIM + db + 9],       W[row0 * DIM + db + 8]);
        v.w = packh(W[(row0 + 8) * DIM + db + 9], W[(row0 + 8) * DIM + db + 8]);
        dst[i] = v;
    } else if (idx < WQF_ENT + WPF_ENT + XF_ENT) {
        int i = idx - WQF_ENT - WPF_ENT;
        int lane = i & 31; int r = i >> 5;
        int nb = r & 511; int ks = r >> 9;
        int g = lane >> 2, tig = lane & 3;
        int n = nb * 8 + g;
        int k0 = ks * 16 + 2 * tig;
        uint2 v;
        v.x = packh(x[(size_t)(k0 + 1) * HW + n], x[(size_t)k0 * HW + n]);
        v.y = packh(x[(size_t)(k0 + 9) * HW + n], x[(size_t)(k0 + 8) * HW + n]);
        Xf[i] = v;
    }
}

// ---------------- tensor-core GEMM: C = W x X + bias ------------------------
template <bool HOUT>
__global__ __launch_bounds__(128) void gemm_tc_kernel(
    const uint4* __restrict__ Wf, const uint2* __restrict__ Xf,
    const float* __restrict__ bias, void* __restrict__ Cout)
{
    int tid = threadIdx.x, w = tid >> 5, lane = tid & 31;
    int g = lane >> 2, tig = lane & 3;
    int mrb = blockIdx.y * 4 + w;
    int nb0 = blockIdx.x * 8;

    float acc[8][4];
    #pragma unroll
    for (int j = 0; j < 8; j++)
        #pragma unroll
        for (int e = 0; e < 4; e++) acc[j][e] = 0.f;

    #pragma unroll
    for (int ks = 0; ks < KS12; ks++) {
        uint4 wa = Wf[(mrb * KS12 + ks) * 32 + lane];
        #pragma unroll
        for (int j = 0; j < 8; j++) {
            uint2 xb = Xf[((ks << 9) + nb0 + j) * 32 + lane];
            mma16(acc[j], (const uint32_t*)&wa, xb);
        }
    }

    int row0 = mrb * 16 + g;
    float b0 = bias[row0], b1 = bias[row0 + 8];
    if (HOUT) {
        __half* C = (__half*)Cout;
        #pragma unroll
        for (int j = 0; j < 8; j++) {
            int colb = (nb0 + j) * 8 + 2 * tig;
            *(uint32_t*)(C + (size_t)row0 * HW + colb) =
                packh(acc[j][1] + b0, acc[j][0] + b0);
            *(uint32_t*)(C + (size_t)(row0 + 8) * HW + colb) =
                packh(acc[j][3] + b1, acc[j][2] + b1);
        }
    } else {
        float* C = (float*)Cout;
        #pragma unroll
        for (int j = 0; j < 8; j++)
            #pragma unroll
            for (int e = 0; e < 4; e++) {
                int row = row0 + ((e >> 1) << 3);
                int col = (nb0 + j) * 8 + 2 * tig + (e & 1);
                C[(size_t)row * HW + col] = acc[j][e] + ((e >> 1) ? b1 : b0);
            }
    }
}

// ---------------- 3x3 depthwise conv: fp16 I/O, f32 smem tile --------------
__global__ __launch_bounds__(256) void dwconv_kernel(
    const __half* __restrict__ in, const float* __restrict__ w,
    const float* __restrict__ b, __half* __restrict__ out)
{
    __shared__ float sm[66 * 66];
    int c = blockIdx.x;
    const __half* ip = in + (size_t)c * HW;

    for (int i = threadIdx.x; i < 66 * 66; i += 256) {
        int y = i / 66, x = i - y * 66;
        int gy = y - 1, gx = x - 1;
        float v = 0.f;
        if ((unsigned)gy < 64u && (unsigned)gx < 64u)
            v = __half2float(ip[gy * 64 + gx]);
        sm[i] = v;
    }
    float wr[9];
    #pragma unroll
    for (int k = 0; k < 9; k++) wr[k] = w[c * 9 + k];
    float bb = b[c];
    __syncthreads();

    __half* op = out + (size_t)c * HW;
    #pragma unroll
    for (int k = 0; k < 16; k++) {
        int pix = threadIdx.x + k * 256;
        int y = pix >> 6, x = pix & 63;
        const float* s0 = sm + y * 66 + x;
        float acc = bb;
        acc += wr[0] * s0[0]   + wr[1] * s0[1]   + wr[2] * s0[2];
        acc += wr[3] * s0[66]  + wr[4] * s0[67]  + wr[5] * s0[68];
        acc += wr[6] * s0[132] + wr[7] * s0[133] + wr[8] * s0[134];
        op[pix] = __float2half(acc);
    }
}

// ---------------- per-(head,n) inverse L2 norms ----------------
__global__ __launch_bounds__(256) void norm_kernel(
    const __half* __restrict__ qkv, float* __restrict__ invq, float* __restrict__ invk)
{
    int idx = blockIdx.x * 256 + threadIdx.x;
    int h = idx / HW, n = idx % HW;
    const __half* qb = qkv + (size_t)(h * D) * HW + n;
    const __half* kb = qkv + (size_t)(DIM + h * D) * HW + n;
    float sq = 0.f, sk = 0.f;
    #pragma unroll
    for (int d = 0; d < D; d++) {
        float a = __half2float(qb[(size_t)d * HW]); sq += a * a;
        float c = __half2float(kb[(size_t)d * HW]); sk += c * c;
    }
    invq[idx] = 1.0f / fmaxf(sqrtf(sq), 1e-12f);
    invk[idx] = 1.0f / fmaxf(sqrtf(sk), 1e-12f);
}

// ---------------- build Q/K/V fragment arrays in gmem (all f16x2) ---------
__global__ __launch_bounds__(256) void prep_kernel(
    const __half* __restrict__ qkv, const float* __restrict__ invq,
    const float* __restrict__ invk, const float* __restrict__ temp,
    uint4* __restrict__ Qf, uint2* __restrict__ Kf, uint2* __restrict__ Vf)
{
    int idx = blockIdx.x * 256 + threadIdx.x;
    if (idx < QF_LANES) {
        int lane = idx & 31; int r = idx >> 5;
        int ks = r % 3; r /= 3;
        int rb = r & 255; int h = r >> 8;
        int g = lane >> 2, tig = lane & 3;
        float cst = temp[h] * 1.44269504088896f;
        const __half* qg = qkv + (size_t)(h * D) * HW;
        int row0 = rb * 16 + g;
        float iq0 = invq[h * HW + row0] * cst;
        float iq1 = invq[h * HW + row0 + 8] * cst;
        int db = ks * 16 + 2 * tig;
        uint4 v;
        v.x = packh(__half2float(qg[(size_t)(db + 1) * HW + row0]) * iq0,
                    __half2float(qg[(size_t)db * HW + row0]) * iq0);
        v.y = packh(__half2float(qg[(size_t)(db + 1) * HW + row0 + 8]) * iq1,
                    __half2float(qg[(size_t)db * HW + row0 + 8]) * iq1);
        v.z = packh(__half2float(qg[(size_t)(db + 9) * HW + row0]) * iq0,
                    __half2float(qg[(size_t)(db + 8) * HW + row0]) * iq0);
        v.w = packh(__half2float(qg[(size_t)(db + 9) * HW + row0 + 8]) * iq1,
                    __half2float(qg[(size_t)(db + 8) * HW + row0 + 8]) * iq1);
        Qf[idx] = v;
    } else if (idx < QF_LANES + KF_LANES) {
        int i = idx - QF_LANES;
        int lane = i & 31; int r = i >> 5;
        int j = r & 7; r >>= 3;
        int ks = r % 3; r /= 3;
        int t = r & 63; int h = r >> 6;
        int g = lane >> 2, tig = lane & 3;
        int key = t * 64 + j * 8 + g;
        float ik = invk[h * HW + key];
        const __half* kg = qkv + (size_t)(DIM + h * D) * HW;
        int db = ks * 16 + 2 * tig;
        uint2 v;
        v.x = packh(__half2float(kg[(size_t)(db + 1) * HW + key]) * ik,
                    __half2float(kg[(size_t)db * HW + key]) * ik);
        v.y = packh(__half2float(kg[(size_t)(db + 9) * HW + key]) * ik,
                    __half2float(kg[(size_t)(db + 8) * HW + key]) * ik);
        Kf[i] = v;
    } else if (idx < QF_LANES + KF_LANES + VF_LANES) {
        int i = idx - QF_LANES - KF_LANES;
        int lane = i & 31; int r = i >> 5;
        int j2 = r % 6; r /= 6;
        int u = r & 3; r >>= 2;
        int t = r & 63; int h = r >> 6;
        int g = lane >> 2, tig = lane & 3;
        int d = 8 * j2 + g;
        const __half* vp = qkv + (size_t)(2 * DIM + h * D) * HW + (size_t)d * HW;
        int k0 = t * 64 + u * 16 + 2 * tig;
        uint2 o;
        o.x = packh(__half2float(vp[k0 + 1]), __half2float(vp[k0]));
        o.y = packh(__half2float(vp[k0 + 9]), __half2float(vp[k0 + 8]));
        Vf[i] = o;
    }
}

// ---------------- attention: 256q CTA (8 warps), cp.async K/V --------------
#define TILE_U2 (24 * 32)      // uint2 entries per K (or V) tile = 6KB

__global__ __launch_bounds__(256, 2) void flash_mma_kernel(
    const uint4* __restrict__ Qf, const uint2* __restrict__ Kf,
    const uint2* __restrict__ Vf,
    uint32_t* __restrict__ po, float* __restrict__ pl)
{
    __shared__ uint2 sK[2][TILE_U2];
    __shared__ uint2 sV[2][TILE_U2];

    int tid = threadIdx.x, w = tid >> 5, lane = tid & 31;
    int g = lane >> 2, tig = lane & 3;
    int h = blockIdx.y, sp = blockIdx.z;
    int n0 = blockIdx.x * 256;
    int rb16 = (n0 >> 4) + w * 2;

    uint4 qa[2][3];
    #pragma unroll
    for (int rb = 0; rb < 2; rb++)
        #pragma unroll
        for (int ks = 0; ks < 3; ks++)
            qa[rb][ks] = Qf[((size_t)((h * 256 + rb16 + rb) * 3 + ks)) * 32 + lane];

    float oacc[2][7][4];
    #pragma unroll
    for (int rb = 0; rb < 2; rb++)
        #pragma unroll
        for (int j = 0; j < 7; j++)
            #pragma unroll
            for (int e = 0; e < 4; e++) oacc[rb][j][e] = 0.f;

    const uint2 ones = make_uint2(0x3C003C00u, 0x3C003C00u);
    int t0 = sp * NTT;

    {
        const uint2* srcK = Kf + (size_t)(h * 64 + t0) * TILE_U2;
        const uint2* srcV = Vf + (size_t)(h * 64 + t0) * TILE_U2;
        #pragma unroll
        for (int i = 0; i < 3; i++) {
            int c = tid + i * 256;   // 0..767 : 384 K chunks + 384 V chunks
            if (c < 384)
                cpasync16(smem_u32(&sK[0][c * 2]), srcK + c * 2);
            else
                cpasync16(smem_u32(&sV[0][(c - 384) * 2]), srcV + (c - 384) * 2);
        }
        CP_COMMIT();
    }

    for (int tt = 0; tt < NTT; tt++) {
        int cur = tt & 1;
        if (tt + 1 < NTT) {
            const uint2* srcK = Kf + (size_t)(h * 64 + t0 + tt + 1) * TILE_U2;
            const uint2* srcV = Vf + (size_t)(h * 64 + t0 + tt + 1) * TILE_U2;
            int nb = (tt + 1) & 1;
            #pragma unroll
            for (int i = 0; i < 3; i++) {
                int c = tid + i * 256;
                if (c < 384)
                    cpasync16(smem_u32(&sK[nb][c * 2]), srcK + c * 2);
                else
                    cpasync16(smem_u32(&sV[nb][(c - 384) * 2]), srcV + (c - 384) * 2);
            }
            CP_COMMIT();
            CP_WAIT(1);
        } else {
            CP_WAIT(0);
        }
        __syncthreads();

        const uint2* kf = sK[cur];
        const uint2* vf = sV[cur];

        float sacc[2][8][4];
        #pragma unroll
        for (int rb = 0; rb < 2; rb++)
            #pragma unroll
            for (int j = 0; j < 8; j++)
                #pragma unroll
                for (int e = 0; e < 4; e++) sacc[rb][j][e] = 0.f;

        #pragma unroll
        for (int ks = 0; ks < 3; ks++) {
            #pragma unroll
            for (int j = 0; j < 8; j++) {
                uint2 kb = kf[(ks * 8 + j) * 32 + lane];
                mma16(sacc[0][j], (const uint32_t*)&qa[0][ks], kb);
                mma16(sacc[1][j], (const uint32_t*)&qa[1][ks], kb);
            }
        }

        uint32_t pf[2][4][4];
        #pragma unroll
        for (int rb = 0; rb < 2; rb++)
            #pragma unroll
            for (int u = 0; u < 4; u++) {
                pf[rb][u][0] = ex2h2(packh(sacc[rb][2 * u][1],     sacc[rb][2 * u][0]));
                pf[rb][u][1] = ex2h2(packh(sacc[rb][2 * u][3],     sacc[rb][2 * u][2]));
                pf[rb][u][2] = ex2h2(packh(sacc[rb][2 * u + 1][1], sacc[rb][2 * u + 1][0]));
                pf[rb][u][3] = ex2h2(packh(sacc[rb][2 * u + 1][3], sacc[rb][2 * u + 1][2]));
            }

        #pragma unroll
        for (int u = 0; u < 4; u++) {
            #pragma unroll
            for (int j2 = 0; j2 < 6; j2++) {
                uint2 vb = vf[(u * 6 + j2) * 32 + lane];
                mma16(oacc[0][j2], pf[0][u], vb);
                mma16(oacc[1][j2], pf[1][u], vb);
            }
            mma16(oacc[0][6], pf[0][u], ones);
            mma16(oacc[1][6], pf[1][u], ones);
        }
        __syncthreads();
    }

    int sh = sp * HEADS + h;
    if (tig == 0) {
        #pragma unroll
        for (int rb = 0; rb < 2; rb++) {
            int row = n0 + w * 32 + rb * 16 + g;
            pl[(size_t)sh * HW + row]     = oacc[rb][6][0];
            pl[(size_t)sh * HW + row + 8] = oacc[rb][6][2];
        }
    }
    #pragma unroll
    for (int rb = 0; rb < 2; rb++) {
        int row = n0 + w * 32 + rb * 16 + g;
        #pragma unroll
        for (int j2 = 0; j2 < 6; j2++) {
            int pd = 4 * j2 + tig;
            po[(size_t)(sh * 24 + pd) * HW + row] =
                packh(oacc[rb][j2][1], oacc[rb][j2][0]);
            po[(size_t)(sh * 24 + pd) * HW + row + 8] =
                packh(oacc[rb][j2][3], oacc[rb][j2][2]);
        }
    }
}

// ---------------- combine split partials -> att B-frags (fp16) -------------
__global__ __launch_bounds__(256) void combine_frag_kernel(
    const uint32_t* __restrict__ po, const float* __restrict__ pl,
    uint2* __restrict__ Af)
{
    int idx = blockIdx.x * 256 + threadIdx.x;
    if (idx >= AF_ENT) return;
    int lane = idx & 31; int r = idx >> 5;
    int nb = r & 511; int ks = r >> 9;
    int g = lane >> 2, tig = lane & 3;
    int n = nb * 8 + g;
    int k0 = ks * 16 + 2 * tig;

    int ha = k0 / D, hb = (k0 + 8) / D;
    float La = 0.f, Lb = 0.f;
    #pragma unroll
    for (int s = 0; s < SPLITS; s++) {
        La += pl[(size_t)(s * HEADS + ha) * HW + n];
        Lb += pl[(size_t)(s * HEADS + hb) * HW + n];
    }
    float ia = 1.0f / La, ib = 1.0f / Lb;

    float v0 = 0.f, v1 = 0.f, v2 = 0.f, v3 = 0.f;
    int pa_idx = (k0 - ha * D) >> 1;
    int pb_idx = ((k0 + 8) - hb * D) >> 1;
    #pragma unroll
    for (int s = 0; s < SPLITS; s++) {
        uint32_t ua = po[(size_t)((s * HEADS + ha) * 24 + pa_idx) * HW + n];
        uint32_t ub = po[(size_t)((s * HEADS + hb) * 24 + pb_idx) * HW + n];
        __half2 hva = *reinterpret_cast<const __half2*>(&ua);
        __half2 hvb = *reinterpret_cast<const __half2*>(&ub);
        v0 += __low2float(hva);
        v1 += __high2float(hva);
        v2 += __low2float(hvb);
        v3 += __high2float(hvb);
    }
    uint2 o;
    o.x = packh(v1 * ia, v0 * ia);
    o.y = packh(v3 * ib, v2 * ib);
    Af[idx] = o;
}

// ---------------- launch ----------------
extern "C" void kernel_launch(void* const* d_in, const int* in_sizes, int n_in,
                              void* d_out, int out_size)
{
    const float* x      = (const float*)d_in[0];
    const float* w_qkv  = (const float*)d_in[1];
    const float* b_qkv  = (const float*)d_in[2];
    const float* w_dw   = (const float*)d_in[3];
    const float* b_dw   = (const float*)d_in[4];
    const float* w_proj = (const float*)d_in[5];
    const float* b_proj = (const float*)d_in[6];
    const float* temp   = (const float*)d_in[7];
    float* out = (float*)d_out;

    __half *qkv1, *qkv2;
    float *invq, *invk, *pl;
    uint32_t* po;
    uint4 *Qf, *Wqf, *Wpf; uint2 *Kf, *Vf, *Xf, *Af;
    cudaGetSymbolAddress((void**)&qkv1, g_qkv1);
    cudaGetSymbolAddress((void**)&qkv2, g_qkv2);
    cudaGetSymbolAddress((void**)&invq, g_invq);
    cudaGetSymbolAddress((void**)&invk, g_invk);
    cudaGetSymbolAddress((void**)&po,   g_po);
    cudaGetSymbolAddress((void**)&pl,   g_pl);
    cudaGetSymbolAddress((void**)&Qf,   g_Qf);
    cudaGetSymbolAddress((void**)&Kf,   g_Kf);
    cudaGetSymbolAddress((void**)&Vf,   g_Vf);
    cudaGetSymbolAddress((void**)&Wqf,  g_Wqf);
    cudaGetSymbolAddress((void**)&Wpf,  g_Wpf);
    cudaGetSymbolAddress((void**)&Xf,   g_Xf);
    cudaGetSymbolAddress((void**)&Af,   g_Af);

    // 1) merged weight + x fragment prep
    {
        int total = WQF_ENT + WPF_ENT + XF_ENT;
        prep0_kernel<<<(total + 255) / 256, 256>>>(w_qkv, w_proj, x, Wqf, Wpf, Xf);
    }
    // 2) qkv 1x1 conv (tensor cores, half output)
    {
        dim3 grid(HW / 64, (3 * DIM) / 64);
        gemm_tc_kernel<true><<<grid, 128>>>(Wqf, Xf, b_qkv, qkv1);
    }
    // 3) depthwise (smem halo, fp16 I/O)
    dwconv_kernel<<<3 * DIM, 256>>>(qkv1, w_dw, b_dw, qkv2);
    // 4) inverse norms
    norm_kernel<<<(HEADS * HW) / 256, 256>>>(qkv2, invq, invk);
    // 5) attention fragment prep
    {
        int total = QF_LANES + KF_LANES + VF_LANES;
        prep_kernel<<<(total + 255) / 256, 256>>>(qkv2, invq, invk, temp, Qf, Kf, Vf);
    }
    // 6) attention (256 queries per CTA)
    {
        dim3 grid(HW / 256, HEADS, SPLITS);
        flash_mma_kernel<<<grid, 256>>>(Qf, Kf, Vf, po, pl);
    }
    // 7) combine -> att B-frags
    combine_frag_kernel<<<(AF_ENT + 255) / 256, 256>>>(po, pl, Af);
    // 8) output projection (tensor cores, f32 output)
    {
        dim3 grid(HW / 64, DIM / 64);
        gemm_tc_kernel<false><<<grid, 128>>>(Wpf, Af, b_proj, out);
    }
}

// round 15
// speedup vs baseline: 1.1065x; 1.1065x over previous
#include <cuda_runtime.h>
#include <cuda_fp16.h>
#include <cuda_bf16.h>
#include <cstdint>

#define DIM    192
#define HEADS  4
#define D      48
#define HW     4096
#define BKT    64              // keys per tile
#define SPLITS 8
#define SKEYS  (HW / SPLITS)   // 512 keys per split
#define NTT    (SKEYS / BKT)   // 8 tiles per split
#define KS12   12              // 192/16 k-steps for the 1x1 convs

// fragment array sizes (entries)
#define QF_LANES (HEADS * 256 * 3 * 32)          // uint4 entries
#define KF_LANES (HEADS * 64 * 3 * 8 * 32)       // uint2 entries
#define VF_LANES (HEADS * 64 * 4 * 6 * 32)       // uint2 entries
#define WQF_ENT  (36 * KS12 * 32)                // uint4: w_qkv A-frags
#define WPF_ENT  (12 * KS12 * 32)                // uint4: w_proj A-frags
#define XF_ENT   (KS12 * 512 * 32)               // uint2: x B-frags
#define AF_ENT   (KS12 * 512 * 32)               // uint2: att B-frags

// ---------------- scratch ----------------
__device__ __half   g_qkv1[3 * DIM * HW];
__device__ __half   g_qkv2[3 * DIM * HW];
__device__ float    g_invq[HEADS * HW];
__device__ float    g_invk[HEADS * HW];
__device__ uint32_t g_po  [SPLITS * HEADS * 24 * HW];   // packed half2 pairs
__device__ float    g_pl  [SPLITS * HEADS * HW];
__device__ uint4    g_Qf [QF_LANES];
__device__ uint2    g_Kf [KF_LANES];
__device__ uint2    g_Vf [VF_LANES];
__device__ uint4    g_Wqf[WQF_ENT];
__device__ uint4    g_Wpf[WPF_ENT];
__device__ uint2    g_Xf [XF_ENT];
__device__ uint2    g_Af [AF_ENT];

// ---------------- helpers ----------------
__device__ __forceinline__ uint32_t packh(float hi, float lo) {
    uint32_t r; asm("cvt.rn.f16x2.f32 %0, %1, %2;" : "=r"(r) : "f"(hi), "f"(lo));
    return r;
}
__device__ __forceinline__ uint32_t ex2h2(uint32_t x) {
    uint32_t y; asm("ex2.approx.f16x2 %0, %1;" : "=r"(y) : "r"(x));
    return y;
}
__device__ __forceinline__ void mma16(float* d, const uint32_t* a, uint2 b) {
    asm volatile("mma.sync.aligned.m16n8k16.row.col.f32.f16.f16.f32 "
        "{%0,%1,%2,%3}, {%4,%5,%6,%7}, {%8,%9}, {%0,%1,%2,%3};"
        : "+f"(d[0]), "+f"(d[1]), "+f"(d[2]), "+f"(d[3])
        : "r"(a[0]), "r"(a[1]), "r"(a[2]), "r"(a[3]),
          "r"(b.x), "r"(b.y));
}
__device__ __forceinline__ uint32_t smem_u32(const void* p) {
    uint32_t a;
    asm("{ .reg .u64 t; cvta.to.shared.u64 t, %1; cvt.u32.u64 %0, t; }"
        : "=r"(a) : "l"(p));
    return a;
}
__device__ __forceinline__ void cpasync16(uint32_t saddr, const void* gptr) {
    asm volatile("cp.async.ca.shared.global [%0], [%1], 16;"
                 :: "r"(saddr), "l"(gptr) : "memory");
}
#define CP_COMMIT()  asm volatile("cp.async.commit_group;" ::: "memory")
#define CP_WAIT(n)   asm volatile("cp.async.wait_group %0;" :: "n"(n) : "memory")

// ---------------- merged weight + x fragment prep (fp16) -------------------
__global__ __launch_bounds__(256) void prep0_kernel(
    const float* __restrict__ w_qkv, const float* __restrict__ w_proj,
    const float* __restrict__ x,
    uint4* __restrict__ Wqf, uint4* __restrict__ Wpf, uint2* __restrict__ Xf)
{
    int idx = blockIdx.x * 256 + threadIdx.x;
    if (idx < WQF_ENT + WPF_ENT) {
        const float* W;
        uint4* dst;
        int i;
        if (idx < WQF_ENT) { W = w_qkv; dst = Wqf; i = idx; }
        else { W = w_proj; dst = Wpf; i = idx - WQF_ENT; }
        int lane = i & 31; int r = i >> 5;
        int ks = r % KS12; int mrb = r / KS12;
        int g = lane >> 2, tig = lane & 3;
        int row0 = mrb * 16 + g;
        int db = ks * 16 + 2 * tig;
        uint4 v;
        v.x = packh(W[row0 * DIM + db + 1],       W[row0 * DIM + db]);
        v.y = packh(W[(row0 + 8) * DIM + db + 1], W[(row0 + 8) * DIM + db]);
        v.z = packh(W[row0 * DIM + db + 9],       W[row0 * DIM + db + 8]);
        v.w = packh(W[(row0 + 8) * DIM + db + 9], W[(row0 + 8) * DIM + db + 8]);
        dst[i] = v;
    } else if (idx < WQF_ENT + WPF_ENT + XF_ENT) {
        int i = idx - WQF_ENT - WPF_ENT;
        int lane = i & 31; int r = i >> 5;
        int nb = r & 511; int ks = r >> 9;
        int g = lane >> 2, tig = lane & 3;
        int n = nb * 8 + g;
        int k0 = ks * 16 + 2 * tig;
        uint2 v;
        v.x = packh(x[(size_t)(k0 + 1) * HW + n], x[(size_t)k0 * HW + n]);
        v.y = packh(x[(size_t)(k0 + 9) * HW + n], x[(size_t)(k0 + 8) * HW + n]);
        Xf[i] = v;
    }
}

// ---------------- tensor-core GEMM: C = W x X + bias ------------------------
template <bool HOUT>
__global__ __launch_bounds__(128) void gemm_tc_kernel(
    const uint4* __restrict__ Wf, const uint2* __restrict__ Xf,
    const float* __restrict__ bias, void* __restrict__ Cout)
{
    int tid = threadIdx.x, w = tid >> 5, lane = tid & 31;
    int g = lane >> 2, tig = lane & 3;
    int mrb = blockIdx.y * 4 + w;
    int nb0 = blockIdx.x * 8;

    float acc[8][4];
    #pragma unroll
    for (int j = 0; j < 8; j++)
        #pragma unroll
        for (int e = 0; e < 4; e++) acc[j][e] = 0.f;

    #pragma unroll
    for (int ks = 0; ks < KS12; ks++) {
        uint4 wa = Wf[(mrb * KS12 + ks) * 32 + lane];
        #pragma unroll
        for (int j = 0; j < 8; j++) {
            uint2 xb = Xf[((ks << 9) + nb0 + j) * 32 + lane];
            mma16(acc[j], (const uint32_t*)&wa, xb);
        }
    }

    int row0 = mrb * 16 + g;
    float b0 = bias[row0], b1 = bias[row0 + 8];
    if (HOUT) {
        __half* C = (__half*)Cout;
        #pragma unroll
        for (int j = 0; j < 8; j++) {
            int colb = (nb0 + j) * 8 + 2 * tig;
            *(uint32_t*)(C + (size_t)row0 * HW + colb) =
                packh(acc[j][1] + b0, acc[j][0] + b0);
            *(uint32_t*)(C + (size_t)(row0 + 8) * HW + colb) =
                packh(acc[j][3] + b1, acc[j][2] + b1);
        }
    } else {
        float* C = (float*)Cout;
        #pragma unroll
        for (int j = 0; j < 8; j++)
            #pragma unroll
            for (int e = 0; e < 4; e++) {
                int row = row0 + ((e >> 1) << 3);
                int col = (nb0 + j) * 8 + 2 * tig + (e & 1);
                C[(size_t)row * HW + col] = acc[j][e] + ((e >> 1) ? b1 : b0);
            }
    }
}

// ---------------- 3x3 depthwise conv: fp16 I/O, f32 smem tile --------------
__global__ __launch_bounds__(256) void dwconv_kernel(
    const __half* __restrict__ in, const float* __restrict__ w,
    const float* __restrict__ b, __half* __restrict__ out)
{
    __shared__ float sm[66 * 66];
    int c = blockIdx.x;
    const __half* ip = in + (size_t)c * HW;

    for (int i = threadIdx.x; i < 66 * 66; i += 256) {
        int y = i / 66, x = i - y * 66;
        int gy = y - 1, gx = x - 1;
        float v = 0.f;
        if ((unsigned)gy < 64u && (unsigned)gx < 64u)
            v = __half2float(ip[gy * 64 + gx]);
        sm[i] = v;
    }
    float wr[9];
    #pragma unroll
    for (int k = 0; k < 9; k++) wr[k] = w[c * 9 + k];
    float bb = b[c];
    __syncthreads();

    __half* op = out + (size_t)c * HW;
    #pragma unroll
    for (int k = 0; k < 16; k++) {
        int pix = threadIdx.x + k * 256;
        int y = pix >> 6, x = pix & 63;
        const float* s0 = sm + y * 66 + x;
        float acc = bb;
        acc += wr[0] * s0[0]   + wr[1] * s0[1]   + wr[2] * s0[2];
        acc += wr[3] * s0[66]  + wr[4] * s0[67]  + wr[5] * s0[68];
        acc += wr[6] * s0[132] + wr[7] * s0[133] + wr[8] * s0[134];
        op[pix] = __float2half(acc);
    }
}

// ---------------- inverse L2 norms: 8-way d-split + smem reduce ------------
// Block: 256 threads = 8 warps. Warp w sums d-chunk [6w, 6w+6) for 32 (h,n).
// Grid: HEADS*HW/32 = 512 blocks.
__global__ __launch_bounds__(256) void norm_kernel(
    const __half* __restrict__ qkv, float* __restrict__ invq, float* __restrict__ invk)
{
    __shared__ float psq[8][32];
    __shared__ float psk[8][32];
    int w = threadIdx.x >> 5, lane = threadIdx.x & 31;
    int base = blockIdx.x * 32;            // first (h,n) pair of this block
    int h = base / HW, n0 = base % HW;     // all 32 pairs share h (HW % 32 == 0)
    int n = n0 + lane;

    const __half* qb = qkv + ((size_t)(h * D + w * 6)) * HW + n;
    const __half* kb = qkv + ((size_t)(DIM + h * D + w * 6)) * HW + n;
    float sq = 0.f, sk = 0.f;
    #pragma unroll
    for (int d = 0; d < 6; d++) {
        float a = __half2float(qb[(size_t)d * HW]); sq += a * a;
        float c = __half2float(kb[(size_t)d * HW]); sk += c * c;
    }
    psq[w][lane] = sq;
    psk[w][lane] = sk;
    __syncthreads();

    if (w == 0) {
        float tq = 0.f, tk = 0.f;
        #pragma unroll
        for (int i = 0; i < 8; i++) { tq += psq[i][lane]; tk += psk[i][lane]; }
        invq[base + lane] = 1.0f / fmaxf(sqrtf(tq), 1e-12f);
        invk[base + lane] = 1.0f / fmaxf(sqrtf(tk), 1e-12f);
    }
}

// ---------------- build Q/K/V fragment arrays in gmem (all f16x2) ---------
__global__ __launch_bounds__(256) void prep_kernel(
    const __half* __restrict__ qkv, const float* __restrict__ invq,
    const float* __restrict__ invk, const float* __restrict__ temp,
    uint4* __restrict__ Qf, uint2* __restrict__ Kf, uint2* __restrict__ Vf)
{
    int idx = blockIdx.x * 256 + threadIdx.x;
    if (idx < QF_LANES) {
        int lane = idx & 31; int r = idx >> 5;
        int ks = r % 3; r /= 3;
        int rb = r & 255; int h = r >> 8;
        int g = lane >> 2, tig = lane & 3;
        float cst = temp[h] * 1.44269504088896f;
        const __half* qg = qkv + (size_t)(h * D) * HW;
        int row0 = rb * 16 + g;
        float iq0 = invq[h * HW + row0] * cst;
        float iq1 = invq[h * HW + row0 + 8] * cst;
        int db = ks * 16 + 2 * tig;
        uint4 v;
        v.x = packh(__half2float(qg[(size_t)(db + 1) * HW + row0]) * iq0,
                    __half2float(qg[(size_t)db * HW + row0]) * iq0);
        v.y = packh(__half2float(qg[(size_t)(db + 1) * HW + row0 + 8]) * iq1,
                    __half2float(qg[(size_t)db * HW + row0 + 8]) * iq1);
        v.z = packh(__half2float(qg[(size_t)(db + 9) * HW + row0]) * iq0,
                    __half2float(qg[(size_t)(db + 8) * HW + row0]) * iq0);
        v.w = packh(__half2float(qg[(size_t)(db + 9) * HW + row0 + 8]) * iq1,
                    __half2float(qg[(size_t)(db + 8) * HW + row0 + 8]) * iq1);
        Qf[idx] = v;
    } else if (idx < QF_LANES + KF_LANES) {
        int i = idx - QF_LANES;
        int lane = i & 31; int r = i >> 5;
        int j = r & 7; r >>= 3;
        int ks = r % 3; r /= 3;
        int t = r & 63; int h = r >> 6;
        int g = lane >> 2, tig = lane & 3;
        int key = t * 64 + j * 8 + g;
        float ik = invk[h * HW + key];
        const __half* kg = qkv + (size_t)(DIM + h * D) * HW;
        int db = ks * 16 + 2 * tig;
        uint2 v;
        v.x = packh(__half2float(kg[(size_t)(db + 1) * HW + key]) * ik,
                    __half2float(kg[(size_t)db * HW + key]) * ik);
        v.y = packh(__half2float(kg[(size_t)(db + 9) * HW + key]) * ik,
                    __half2float(kg[(size_t)(db + 8) * HW + key]) * ik);
        Kf[i] = v;
    } else if (idx < QF_LANES + KF_LANES + VF_LANES) {
        int i = idx - QF_LANES - KF_LANES;
        int lane = i & 31; int r = i >> 5;
        int j2 = r % 6; r /= 6;
        int u = r & 3; r >>= 2;
        int t = r & 63; int h = r >> 6;
        int g = lane >> 2, tig = lane & 3;
        int d = 8 * j2 + g;
        const __half* vp = qkv + (size_t)(2 * DIM + h * D) * HW + (size_t)d * HW;
        int k0 = t * 64 + u * 16 + 2 * tig;
        uint2 o;
        o.x = packh(__half2float(vp[k0 + 1]), __half2float(vp[k0]));
        o.y = packh(__half2float(vp[k0 + 9]), __half2float(vp[k0 + 8]));
        Vf[i] = o;
    }
}

// ---------------- attention: 128q CTA, cp.async K/V, packed-half po --------
#define TILE_U2 (24 * 32)      // uint2 entries per K (or V) tile = 6KB

__global__ __launch_bounds__(128, 3) void flash_mma_kernel(
    const uint4* __restrict__ Qf, const uint2* __restrict__ Kf,
    const uint2* __restrict__ Vf,
    uint32_t* __restrict__ po, float* __restrict__ pl)
{
    __shared__ uint2 sK[2][TILE_U2];
    __shared__ uint2 sV[2][TILE_U2];

    int tid = threadIdx.x, w = tid >> 5, lane = tid & 31;
    int g = lane >> 2, tig = lane & 3;
    int h = blockIdx.y, sp = blockIdx.z;
    int n0 = blockIdx.x * 128;
    int rb16 = (n0 >> 4) + w * 2;

    uint4 qa[2][3];
    #pragma unroll
    for (int rb = 0; rb < 2; rb++)
        #pragma unroll
        for (int ks = 0; ks < 3; ks++)
            qa[rb][ks] = Qf[((size_t)((h * 256 + rb16 + rb) * 3 + ks)) * 32 + lane];

    float oacc[2][7][4];
    #pragma unroll
    for (int rb = 0; rb < 2; rb++)
        #pragma unroll
        for (int j = 0; j < 7; j++)
            #pragma unroll
            for (int e = 0; e < 4; e++) oacc[rb][j][e] = 0.f;

    const uint2 ones = make_uint2(0x3C003C00u, 0x3C003C00u);
    int t0 = sp * NTT;

    {
        const uint2* srcK = Kf + (size_t)(h * 64 + t0) * TILE_U2;
        const uint2* srcV = Vf + (size_t)(h * 64 + t0) * TILE_U2;
        #pragma unroll
        for (int i = 0; i < 3; i++) {
            int c = tid + i * 128;
            cpasync16(smem_u32(&sK[0][c * 2]), srcK + c * 2);
            cpasync16(smem_u32(&sV[0][c * 2]), srcV + c * 2);
        }
        CP_COMMIT();
    }

    for (int tt = 0; tt < NTT; tt++) {
        int cur = tt & 1;
        if (tt + 1 < NTT) {
            const uint2* srcK = Kf + (size_t)(h * 64 + t0 + tt + 1) * TILE_U2;
            const uint2* srcV = Vf + (size_t)(h * 64 + t0 + tt + 1) * TILE_U2;
            int nb = (tt + 1) & 1;
            #pragma unroll
            for (int i = 0; i < 3; i++) {
                int c = tid + i * 128;
                cpasync16(smem_u32(&sK[nb][c * 2]), srcK + c * 2);
                cpasync16(smem_u32(&sV[nb][c * 2]), srcV + c * 2);
            }
            CP_COMMIT();
            CP_WAIT(1);
        } else {
            CP_WAIT(0);
        }
        __syncthreads();

        const uint2* kf = sK[cur];
        const uint2* vf = sV[cur];

        float sacc[2][8][4];
        #pragma unroll
        for (int rb = 0; rb < 2; rb++)
            #pragma unroll
            for (int j = 0; j < 8; j++)
                #pragma unroll
                for (int e = 0; e < 4; e++) sacc[rb][j][e] = 0.f;

        #pragma unroll
        for (int ks = 0; ks < 3; ks++) {
            #pragma unroll
            for (int j = 0; j < 8; j++) {
                uint2 kb = kf[(ks * 8 + j) * 32 + lane];
                mma16(sacc[0][j], (const uint32_t*)&qa[0][ks], kb);
                mma16(sacc[1][j], (const uint32_t*)&qa[1][ks], kb);
            }
        }

        uint32_t pf[2][4][4];
        #pragma unroll
        for (int rb = 0; rb < 2; rb++)
            #pragma unroll
            for (int u = 0; u < 4; u++) {
                pf[rb][u][0] = ex2h2(packh(sacc[rb][2 * u][1],     sacc[rb][2 * u][0]));
                pf[rb][u][1] = ex2h2(packh(sacc[rb][2 * u][3],     sacc[rb][2 * u][2]));
                pf[rb][u][2] = ex2h2(packh(sacc[rb][2 * u + 1][1], sacc[rb][2 * u + 1][0]));
                pf[rb][u][3] = ex2h2(packh(sacc[rb][2 * u + 1][3], sacc[rb][2 * u + 1][2]));
            }

        #pragma unroll
        for (int u = 0; u < 4; u++) {
            #pragma unroll
            for (int j2 = 0; j2 < 6; j2++) {
                uint2 vb = vf[(u * 6 + j2) * 32 + lane];
                mma16(oacc[0][j2], pf[0][u], vb);
                mma16(oacc[1][j2], pf[1][u], vb);
            }
            mma16(oacc[0][6], pf[0][u], ones);
            mma16(oacc[1][6], pf[1][u], ones);
        }
        __syncthreads();
    }

    int sh = sp * HEADS + h;
    if (tig == 0) {
        #pragma unroll
        for (int rb = 0; rb < 2; rb++) {
            int row = n0 + w * 32 + rb * 16 + g;
            pl[(size_t)sh * HW + row]     = oacc[rb][6][0];
            pl[(size_t)sh * HW + row + 8] = oacc[rb][6][2];
        }
    }
    #pragma unroll
    for (int rb = 0; rb < 2; rb++) {
        int row = n0 + w * 32 + rb * 16 + g;
        #pragma unroll
        for (int j2 = 0; j2 < 6; j2++) {
            int pd = 4 * j2 + tig;
            po[(size_t)(sh * 24 + pd) * HW + row] =
                packh(oacc[rb][j2][1], oacc[rb][j2][0]);
            po[(size_t)(sh * 24 + pd) * HW + row + 8] =
                packh(oacc[rb][j2][3], oacc[rb][j2][2]);
        }
    }
}

// ---------------- combine split partials -> att B-frags (fp16) -------------
__global__ __launch_bounds__(256) void combine_frag_kernel(
    const uint32_t* __restrict__ po, const float* __restrict__ pl,
    uint2* __restrict__ Af)
{
    int idx = blockIdx.x * 256 + threadIdx.x;
    if (idx >= AF_ENT) return;
    int lane = idx & 31; int r = idx >> 5;
    int nb = r & 511; int ks = r >> 9;
    int g = lane >> 2, tig = lane & 3;
    int n = nb * 8 + g;
    int k0 = ks * 16 + 2 * tig;

    int ha = k0 / D, hb = (k0 + 8) / D;
    float La = 0.f, Lb = 0.f;
    #pragma unroll
    for (int s = 0; s < SPLITS; s++) {
        La += pl[(size_t)(s * HEADS + ha) * HW + n];
        Lb += pl[(size_t)(s * HEADS + hb) * HW + n];
    }
    float ia = 1.0f / La, ib = 1.0f / Lb;

    float v0 = 0.f, v1 = 0.f, v2 = 0.f, v3 = 0.f;
    int pa_idx = (k0 - ha * D) >> 1;
    int pb_idx = ((k0 + 8) - hb * D) >> 1;
    #pragma unroll
    for (int s = 0; s < SPLITS; s++) {
        uint32_t ua = po[(size_t)((s * HEADS + ha) * 24 + pa_idx) * HW + n];
        uint32_t ub = po[(size_t)((s * HEADS + hb) * 24 + pb_idx) * HW + n];
        __half2 hva = *reinterpret_cast<const __half2*>(&ua);
        __half2 hvb = *reinterpret_cast<const __half2*>(&ub);
        v0 += __low2float(hva);
        v1 += __high2float(hva);
        v2 += __low2float(hvb);
        v3 += __high2float(hvb);
    }
    uint2 o;
    o.x = packh(v1 * ia, v0 * ia);
    o.y = packh(v3 * ib, v2 * ib);
    Af[idx] = o;
}

// ---------------- launch ----------------
extern "C" void kernel_launch(void* const* d_in, const int* in_sizes, int n_in,
                              void* d_out, int out_size)
{
    const float* x      = (const float*)d_in[0];
    const float* w_qkv  = (const float*)d_in[1];
    const float* b_qkv  = (const float*)d_in[2];
    const float* w_dw   = (const float*)d_in[3];
    const float* b_dw   = (const float*)d_in[4];
    const float* w_proj = (const float*)d_in[5];
    const float* b_proj = (const float*)d_in[6];
    const float* temp   = (const float*)d_in[7];
    float* out = (float*)d_out;

    __half *qkv1, *qkv2;
    float *invq, *invk, *pl;
    uint32_t* po;
    uint4 *Qf, *Wqf, *Wpf; uint2 *Kf, *Vf, *Xf, *Af;
    cudaGetSymbolAddress((void**)&qkv1, g_qkv1);
    cudaGetSymbolAddress((void**)&qkv2, g_qkv2);
    cudaGetSymbolAddress((void**)&invq, g_invq);
    cudaGetSymbolAddress((void**)&invk, g_invk);
    cudaGetSymbolAddress((void**)&po,   g_po);
    cudaGetSymbolAddress((void**)&pl,   g_pl);
    cudaGetSymbolAddress((void**)&Qf,   g_Qf);
    cudaGetSymbolAddress((void**)&Kf,   g_Kf);
    cudaGetSymbolAddress((void**)&Vf,   g_Vf);
    cudaGetSymbolAddress((void**)&Wqf,  g_Wqf);
    cudaGetSymbolAddress((void**)&Wpf,  g_Wpf);
    cudaGetSymbolAddress((void**)&Xf,   g_Xf);
    cudaGetSymbolAddress((void**)&Af,   g_Af);

    // 1) merged weight + x fragment prep
    {
        int total = WQF_ENT + WPF_ENT + XF_ENT;
        prep0_kernel<<<(total + 255) / 256, 256>>>(w_qkv, w_proj, x, Wqf, Wpf, Xf);
    }
    // 2) qkv 1x1 conv (tensor cores, half output)
    {
        dim3 grid(HW / 64, (3 * DIM) / 64);
        gemm_tc_kernel<true><<<grid, 128>>>(Wqf, Xf, b_qkv, qkv1);
    }
    // 3) depthwise (smem halo, fp16 I/O)
    dwconv_kernel<<<3 * DIM, 256>>>(qkv1, w_dw, b_dw, qkv2);
    // 4) inverse norms (512 CTAs, d-split)
    norm_kernel<<<(HEADS * HW) / 32, 256>>>(qkv2, invq, invk);
    // 5) attention fragment prep
    {
        int total = QF_LANES + KF_LANES + VF_LANES;
        prep_kernel<<<(total + 255) / 256, 256>>>(qkv2, invq, invk, temp, Qf, Kf, Vf);
    }
    // 6) attention (128 queries per CTA)
    {
        dim3 grid(HW / 128, HEADS, SPLITS);
        flash_mma_kernel<<<grid, 128>>>(Qf, Kf, Vf, po, pl);
    }
    // 7) combine -> att B-frags
    combine_frag_kernel<<<(AF_ENT + 255) / 256, 256>>>(po, pl, Af);
    // 8) output projection (tensor cores, f32 output)
    {
        dim3 grid(HW / 64, DIM / 64);
        gemm_tc_kernel<false><<<grid, 128>>>(Wpf, Af, b_proj, out);
    }
}